// round 1
// baseline (speedup 1.0000x reference)
#include <cuda_runtime.h>
#include <cstdint>

#define DD 256          // feature dim
#define HH 512          // hidden dim
#define ROWS 8          // batch rows per block
#define NT 512          // threads per block

// Transposed weights in device scratch (allocation-free per rules).
__device__ float g_W1t[DD * HH];   // [d][j]  (W1 is [H,D])
__device__ float g_W2t[HH * HH];   // [d][j]  (W2 is [H,H])
__device__ float g_W3t[HH * DD];   // [d][j]  (W3 is [D,H])

__global__ void prep_kernel(const float* __restrict__ W1,
                            const float* __restrict__ W2,
                            const float* __restrict__ W3) {
    int idx = blockIdx.x * blockDim.x + threadIdx.x;
    int stride = gridDim.x * blockDim.x;
    // W1 [H,D] -> W1t [D,H]
    for (int i = idx; i < HH * DD; i += stride) {
        int r = i / DD, c = i - r * DD;
        g_W1t[c * HH + r] = W1[i];
    }
    // W2 [H,H] -> W2t [H,H] (transpose)
    for (int i = idx; i < HH * HH; i += stride) {
        int r = i / HH, c = i - r * HH;
        g_W2t[c * HH + r] = W2[i];
    }
    // W3 [D,H] -> W3t [H,D]
    for (int i = idx; i < DD * HH; i += stride) {
        int r = i / HH, c = i - r * HH;
        g_W3t[c * DD + r] = W3[i];
    }
}

__device__ __forceinline__ float f4c(const float4& v, int q) {
    return q == 0 ? v.x : (q == 1 ? v.y : (q == 2 ? v.z : v.w));
}

// One MLP eval for ROWS rows: out = W3*relu(W2*relu(W1*in + b1) + b2) + b3
// in/out: [ROWS][DD] in smem. h1/h2: [ROWS][HH] smem scratch.
// Caller guarantees `in` is fully written + synced. Ends with __syncthreads().
__device__ __forceinline__ void mlp_eval(const float* __restrict__ in,
                                         float* __restrict__ out,
                                         float* __restrict__ h1,
                                         float* __restrict__ h2,
                                         const float* __restrict__ sb1,
                                         const float* __restrict__ sb2,
                                         const float* __restrict__ sb3,
                                         int t) {
    // ---------- layer 1: [ROWS,DD] x W1t[DD,HH] -> h1 [ROWS,HH], relu ----------
    {
        int j = t;                       // NT == HH
        float acc[ROWS];
        float bv = sb1[j];
        #pragma unroll
        for (int r = 0; r < ROWS; r++) acc[r] = bv;
        const float* __restrict__ w = g_W1t + j;
        for (int d0 = 0; d0 < DD; d0 += 4) {
            float4 yv[ROWS];
            #pragma unroll
            for (int r = 0; r < ROWS; r++)
                yv[r] = *(const float4*)(in + r * DD + d0);
            #pragma unroll
            for (int q = 0; q < 4; q++) {
                float wv = w[(size_t)(d0 + q) * HH];
                #pragma unroll
                for (int r = 0; r < ROWS; r++)
                    acc[r] = fmaf(f4c(yv[r], q), wv, acc[r]);
            }
        }
        #pragma unroll
        for (int r = 0; r < ROWS; r++)
            h1[r * HH + j] = fmaxf(acc[r], 0.0f);
    }
    __syncthreads();
    // ---------- layer 2: [ROWS,HH] x W2t[HH,HH] -> h2 [ROWS,HH], relu ----------
    {
        int j = t;
        float acc[ROWS];
        float bv = sb2[j];
        #pragma unroll
        for (int r = 0; r < ROWS; r++) acc[r] = bv;
        const float* __restrict__ w = g_W2t + j;
        for (int d0 = 0; d0 < HH; d0 += 4) {
            float4 yv[ROWS];
            #pragma unroll
            for (int r = 0; r < ROWS; r++)
                yv[r] = *(const float4*)(h1 + r * HH + d0);
            #pragma unroll
            for (int q = 0; q < 4; q++) {
                float wv = w[(size_t)(d0 + q) * HH];
                #pragma unroll
                for (int r = 0; r < ROWS; r++)
                    acc[r] = fmaf(f4c(yv[r], q), wv, acc[r]);
            }
        }
        #pragma unroll
        for (int r = 0; r < ROWS; r++)
            h2[r * HH + j] = fmaxf(acc[r], 0.0f);
    }
    __syncthreads();
    // ---------- layer 3: [ROWS,HH] x W3t[HH,DD] -> out [ROWS,DD] ----------
    {
        int half = t >> 8;               // 0: rows 0..3, 1: rows 4..7
        int j = t & (DD - 1);
        const float* __restrict__ in2 = h2 + half * 4 * HH;
        float acc[4];
        float bv = sb3[j];
        #pragma unroll
        for (int r = 0; r < 4; r++) acc[r] = bv;
        const float* __restrict__ w = g_W3t + j;
        for (int d0 = 0; d0 < HH; d0 += 4) {
            float4 hv[4];
            #pragma unroll
            for (int r = 0; r < 4; r++)
                hv[r] = *(const float4*)(in2 + r * HH + d0);
            #pragma unroll
            for (int q = 0; q < 4; q++) {
                float wv = w[(size_t)(d0 + q) * DD];
                #pragma unroll
                for (int r = 0; r < 4; r++)
                    acc[r] = fmaf(f4c(hv[r], q), wv, acc[r]);
            }
        }
        #pragma unroll
        for (int r = 0; r < 4; r++)
            out[(half * 4 + r) * DD + j] = acc[r];
    }
    __syncthreads();
}

__global__ void __launch_bounds__(NT, 1)
ode_kernel(const float* __restrict__ x0,
           const int* __restrict__ Tp,
           const float* __restrict__ b1,
           const float* __restrict__ b2,
           const float* __restrict__ b3,
           float* __restrict__ out,
           int rows_total) {
    extern __shared__ float sm[];
    float* s_y   = sm;                         // ROWS*DD
    float* s_tmp = s_y   + ROWS * DD;          // ROWS*DD
    float* s_k1  = s_tmp + ROWS * DD;
    float* s_k2  = s_k1  + ROWS * DD;
    float* s_k3  = s_k2  + ROWS * DD;
    float* s_k4  = s_k3  + ROWS * DD;
    float* s_k5  = s_k4  + ROWS * DD;
    float* s_k6  = s_k5  + ROWS * DD;
    float* s_h1  = s_k6  + ROWS * DD;          // ROWS*HH
    float* s_h2  = s_h1  + ROWS * HH;          // ROWS*HH
    float* s_b1  = s_h2  + ROWS * HH;          // HH
    float* s_b2  = s_b1  + HH;                 // HH
    float* s_b3  = s_b2  + HH;                 // DD

    const int t = threadIdx.x;
    const int row0 = blockIdx.x * ROWS;

    const int T = *Tp;                         // low 4 bytes, LE-safe for i32/i64
    const int nint = T - 1;
    const float hs = (float)(10.0 / (double)(nint * 4));

    // Dopri5 coefficients (match reference's f32-converted constants)
    const float A21 = (float)(1.0 / 5.0);
    const float A31 = (float)(3.0 / 40.0),      A32 = (float)(9.0 / 40.0);
    const float A41 = (float)(44.0 / 45.0),     A42 = (float)(-56.0 / 15.0),
                A43 = (float)(32.0 / 9.0);
    const float A51 = (float)(19372.0 / 6561.0), A52 = (float)(-25360.0 / 2187.0),
                A53 = (float)(64448.0 / 6561.0), A54 = (float)(-212.0 / 729.0);
    const float A61 = (float)(9017.0 / 3168.0),  A62 = (float)(-355.0 / 33.0),
                A63 = (float)(46732.0 / 5247.0), A64 = (float)(49.0 / 176.0),
                A65 = (float)(-5103.0 / 18656.0);
    const float B1 = (float)(35.0 / 384.0),  B3 = (float)(500.0 / 1113.0),
                B4 = (float)(125.0 / 192.0), B5 = (float)(-2187.0 / 6784.0),
                B6 = (float)(11.0 / 84.0);

    // Load biases + initial state
    for (int i = t; i < HH; i += NT) { s_b1[i] = b1[i]; s_b2[i] = b2[i]; }
    for (int i = t; i < DD; i += NT) s_b3[i] = b3[i];
    for (int i = t; i < ROWS * DD; i += NT) {
        int r = i / DD;
        s_y[i] = (row0 + r < rows_total) ? x0[(size_t)row0 * DD + i] : 0.0f;
    }
    __syncthreads();

    for (int it = 0; it < nint; it++) {
        for (int ss = 0; ss < 4; ss++) {
            // k1 = f(y)
            mlp_eval(s_y, s_k1, s_h1, s_h2, s_b1, s_b2, s_b3, t);
            for (int i = t; i < ROWS * DD; i += NT)
                s_tmp[i] = fmaf(hs * A21, s_k1[i], s_y[i]);
            __syncthreads();
            // k2
            mlp_eval(s_tmp, s_k2, s_h1, s_h2, s_b1, s_b2, s_b3, t);
            for (int i = t; i < ROWS * DD; i += NT)
                s_tmp[i] = fmaf(hs, fmaf(A31, s_k1[i], A32 * s_k2[i]), s_y[i]);
            __syncthreads();
            // k3
            mlp_eval(s_tmp, s_k3, s_h1, s_h2, s_b1, s_b2, s_b3, t);
            for (int i = t; i < ROWS * DD; i += NT) {
                float s = fmaf(A41, s_k1[i], fmaf(A42, s_k2[i], A43 * s_k3[i]));
                s_tmp[i] = fmaf(hs, s, s_y[i]);
            }
            __syncthreads();
            // k4
            mlp_eval(s_tmp, s_k4, s_h1, s_h2, s_b1, s_b2, s_b3, t);
            for (int i = t; i < ROWS * DD; i += NT) {
                float s = fmaf(A51, s_k1[i],
                          fmaf(A52, s_k2[i],
                          fmaf(A53, s_k3[i], A54 * s_k4[i])));
                s_tmp[i] = fmaf(hs, s, s_y[i]);
            }
            __syncthreads();
            // k5
            mlp_eval(s_tmp, s_k5, s_h1, s_h2, s_b1, s_b2, s_b3, t);
            for (int i = t; i < ROWS * DD; i += NT) {
                float s = fmaf(A61, s_k1[i],
                          fmaf(A62, s_k2[i],
                          fmaf(A63, s_k3[i],
                          fmaf(A64, s_k4[i], A65 * s_k5[i]))));
                s_tmp[i] = fmaf(hs, s, s_y[i]);
            }
            __syncthreads();
            // k6
            mlp_eval(s_tmp, s_k6, s_h1, s_h2, s_b1, s_b2, s_b3, t);
            // y += h*(B1 k1 + B3 k3 + B4 k4 + B5 k5 + B6 k6)
            for (int i = t; i < ROWS * DD; i += NT) {
                float s = fmaf(B1, s_k1[i],
                          fmaf(B3, s_k3[i],
                          fmaf(B4, s_k4[i],
                          fmaf(B5, s_k5[i], B6 * s_k6[i]))));
                s_y[i] = fmaf(hs, s, s_y[i]);
            }
            __syncthreads();
        }
        // store y -> out[b, it, :]  (pred shape [B, T-1, D])
        for (int i = t; i < ROWS * DD; i += NT) {
            int r = i / DD, d = i - r * DD;
            int b = row0 + r;
            if (b < rows_total)
                out[((size_t)b * nint + it) * DD + d] = s_y[i];
        }
        // no sync needed: store only reads s_y; next mlp also only reads s_y
    }
}

extern "C" void kernel_launch(void* const* d_in, const int* in_sizes, int n_in,
                              void* d_out, int out_size) {
    const float* x0 = (const float*)d_in[0];
    const int*   Tp = (const int*)d_in[1];
    const float* W1 = (const float*)d_in[2];
    const float* b1 = (const float*)d_in[3];
    const float* W2 = (const float*)d_in[4];
    const float* b2 = (const float*)d_in[5];
    const float* W3 = (const float*)d_in[6];
    const float* b3 = (const float*)d_in[7];
    float* out = (float*)d_out;

    int rows_total = in_sizes[0] / DD;          // B (x0 has B*1*D elements)
    int nblocks = (rows_total + ROWS - 1) / ROWS;

    size_t smem = (size_t)(8 * ROWS * DD + 2 * ROWS * HH + 2 * HH + DD) * sizeof(float);
    cudaFuncSetAttribute(ode_kernel, cudaFuncAttributeMaxDynamicSharedMemorySize,
                         (int)smem);

    prep_kernel<<<64, 256>>>(W1, W2, W3);
    ode_kernel<<<nblocks, NT, smem>>>(x0, Tp, b1, b2, b3, out, rows_total);
}